// round 12
// baseline (speedup 1.0000x reference)
#include <cuda_runtime.h>
#include <cuda_bf16.h>
#include <cstdint>
#include <climits>

#define DIM    768
#define KC     2048
#define NROWS  16384
#define BM     128               // rows per CTA
#define BNH    1024              // codes per CTA (half the codebook)
#define BN     128               // codes per tile iteration
#define BK     64                // bf16 elems per chunk = 128 B/row
#define CHUNKS (DIM / BK)        // 12
#define NTILE  (BNH / BN)        // 8
#define TOT    (NTILE * CHUNKS)  // 96
#define STAGE  32768             // A 16KB + B 16KB
#define QS8    2048.0f           // int8 score quantum = 4.88e-4
#define QWIN8  6                 // refine window (~2.93e-3)

__device__ float g_enorm[KC];
__device__ float g_zsum[NROWS];
__device__ float g_loss;
__device__ int   g_qmin[NROWS];
__device__ __nv_bfloat16 g_zhi[(size_t)NROWS * DIM];
__device__ __nv_bfloat16 g_ehi[(size_t)KC * DIM];
__device__ signed char g_s8[(size_t)NROWS * KC];   // 32 MiB quantized scores

static __device__ __forceinline__ uint32_t smem_u32(const void* p) {
    uint32_t a;
    asm("{ .reg .u64 t; cvta.to.shared.u64 t, %1; cvt.u32.u64 %0, t; }" : "=r"(a) : "l"(p));
    return a;
}
#define CP_ASYNC16(dst, src) \
    asm volatile("cp.async.cg.shared.global [%0], [%1], 16;" :: "r"(dst), "l"(src))
#define CP_COMMIT() asm volatile("cp.async.commit_group;" ::: "memory")
#define LDMX4(r, addr) \
    asm volatile("ldmatrix.sync.aligned.m8n8.x4.shared.b16 {%0,%1,%2,%3}, [%4];" \
        : "=r"((r)[0]), "=r"((r)[1]), "=r"((r)[2]), "=r"((r)[3]) : "r"(addr))
#define MMA16816(d, a, b0_, b1_) \
    asm volatile("mma.sync.aligned.m16n8k16.row.col.f32.bf16.bf16.f32 " \
        "{%0,%1,%2,%3}, {%4,%5,%6,%7}, {%8,%9}, {%0,%1,%2,%3};" \
        : "+f"((d)[0]), "+f"((d)[1]), "+f"((d)[2]), "+f"((d)[3]) \
        : "r"((a)[0]), "r"((a)[1]), "r"((a)[2]), "r"((a)[3]), "r"(b0_), "r"(b1_))

// -------- fused fp32->bf16 convert + row norm + qmin/loss init (warp/row) --------
__global__ void prep_kernel(const float* __restrict__ src,
                            __nv_bfloat16* __restrict__ dst,
                            float* __restrict__ norms, int nrows) {
    int w    = (blockIdx.x * blockDim.x + threadIdx.x) >> 5;
    int lane = threadIdx.x & 31;
    if (w >= nrows) return;
    const float2* s2 = (const float2*)(src + (size_t)w * DIM);
    __nv_bfloat162* d2 = (__nv_bfloat162*)(dst + (size_t)w * DIM);
    float acc = 0.f;
#pragma unroll
    for (int j = 0; j < DIM / 64; j++) {
        float2 v = s2[lane + j * 32];
        acc = fmaf(v.x, v.x, fmaf(v.y, v.y, acc));
        d2[lane + j * 32] = __halves2bfloat162(__float2bfloat16_rn(v.x),
                                               __float2bfloat16_rn(v.y));
    }
#pragma unroll
    for (int o = 16; o > 0; o >>= 1) acc += __shfl_down_sync(0xffffffffu, acc, o);
    if (lane == 0) {
        norms[w] = acc;
        g_qmin[w] = INT_MAX;        // idempotent init (runs in both prep launches)
        if (w == 0) g_loss = 0.f;
    }
}

// -------- pass 1: bf16 HMMA approx GEMM -> int8 scores + per-row qmin --------
// 256 CTAs x 128 thr (2 CTAs/SM). CTA: 128 rows x 1024 codes.
// 4 warps 2x2, warp tile 64x64. 3-stage ring; cp.async issued in the MMA
// shadow for stage s+2; wait_group 1 so the barrier never waits on loads
// issued during the current iteration.
__global__ __launch_bounds__(128, 2)
void vq_pass1_kernel() {
    extern __shared__ char smem_raw[];
    const uint32_t sb = (smem_u32(smem_raw) + 127u) & ~127u;
    const int tid  = threadIdx.x;
    const int lane = tid & 31;
    const int w    = tid >> 5;
    const int wr   = w >> 1;    // 0..1  rows 64 each
    const int wc   = w & 1;     // 0..1  cols 64 each
    const int rowBase = (blockIdx.x >> 1) * BM;
    const int colBase = (blockIdx.x & 1) * BNH;

    // ---- cp.async addressing: 16 x 16B per thread per stage ----
    const int gr  = tid >> 3;          // base row 0..15
    const int gg  = tid & 7;           // granule 0..7
    const uint32_t swx = (uint32_t)((gg ^ (gr & 7)) << 4);
    const uint32_t da  = (uint32_t)(gr * 128) + swx;            // A dst base
    const uint32_t db  = 16384u + (uint32_t)(gr * 128) + swx;   // B dst base
    const __nv_bfloat16* baseA = g_zhi + (size_t)(rowBase + gr) * DIM + gg * 8;
    const __nv_bfloat16* baseB = g_ehi + (size_t)(colBase + gr) * DIM + gg * 8;

    // ---- ldmatrix lane addressing ----
    const int arow = lane & 15;
    const int agr  = lane >> 4;
    const int brow = (lane & 7) + ((lane >> 4) & 1) * 8;
    const int bgr  = (lane >> 3) & 1;
    uint32_t a_rt[4]; int a_sw[4];
#pragma unroll
    for (int mt = 0; mt < 4; mt++) {
        int r = wr * 64 + mt * 16 + arow;
        a_rt[mt] = r * 128; a_sw[mt] = r & 7;
    }
    uint32_t b_rt[4]; int b_sw[4];
#pragma unroll
    for (int nb = 0; nb < 4; nb++) {
        int r = wc * 64 + nb * 16 + brow;
        b_rt[nb] = r * 128; b_sw[nb] = r & 7;
    }

    float acc[4][8][4];
#pragma unroll
    for (int mt = 0; mt < 4; mt++)
#pragma unroll
        for (int nt = 0; nt < 8; nt++)
#pragma unroll
            for (int q = 0; q < 4; q++) acc[mt][nt][q] = 0.f;

    auto issue_all = [&](int ct, int c, int buf) {
        const uint32_t st = sb + (uint32_t)buf * STAGE;
        const __nv_bfloat16* pa = baseA + c * BK;
#pragma unroll
        for (int k = 0; k < 8; k++)
            CP_ASYNC16(st + da + (uint32_t)k * 2048u, pa + (size_t)k * 16 * DIM);
        const __nv_bfloat16* pb = baseB + (size_t)ct * BN * DIM + c * BK;
#pragma unroll
        for (int k = 0; k < 8; k++)
            CP_ASYNC16(st + db + (uint32_t)k * 2048u, pb + (size_t)k * 16 * DIM);
        CP_COMMIT();
    };

    issue_all(0, 0, 0);     // stage 0
    issue_all(0, 1, 1);     // stage 1
    int cct = 0, ccc = 0;

    for (int s = 0; s < TOT; s++) {
        if (s < TOT - 1) asm volatile("cp.async.wait_group 1;" ::: "memory");
        else             asm volatile("cp.async.wait_group 0;" ::: "memory");
        __syncthreads();

        const int nx    = s + 2;
        const bool donx = nx < TOT;
        const uint32_t nst = sb + (uint32_t)(nx % 3) * STAGE;
        const __nv_bfloat16* npa = baseA + (nx % CHUNKS) * BK;
        const __nv_bfloat16* npb = baseB + (size_t)(nx / CHUNKS) * BN * DIM + (nx % CHUNKS) * BK;

        const uint32_t Ab = sb + (uint32_t)(s % 3) * STAGE;
        const uint32_t Bb = Ab + 16384u;

#pragma unroll
        for (int ks = 0; ks < 4; ks++) {
            const int g0 = ks * 2;
            uint32_t ah[16], bh[16];
#pragma unroll
            for (int mt = 0; mt < 4; mt++) {
                uint32_t ad = Ab + a_rt[mt] + (uint32_t)(((g0 + agr) ^ a_sw[mt]) << 4);
                LDMX4(&ah[mt * 4], ad);
            }
#pragma unroll
            for (int nb = 0; nb < 4; nb++) {
                uint32_t bd = Bb + b_rt[nb] + (uint32_t)(((g0 + bgr) ^ b_sw[nb]) << 4);
                LDMX4(&bh[nb * 4], bd);
            }
            // cp.async issue in the LDSM->MMA dependency shadow (4 per ks)
            if (donx) {
                if (ks < 2) {
#pragma unroll
                    for (int k = ks * 4; k < ks * 4 + 4; k++)
                        CP_ASYNC16(nst + da + (uint32_t)k * 2048u, npa + (size_t)k * 16 * DIM);
                } else {
#pragma unroll
                    for (int k = (ks - 2) * 4; k < (ks - 2) * 4 + 4; k++)
                        CP_ASYNC16(nst + db + (uint32_t)k * 2048u, npb + (size_t)k * 16 * DIM);
                }
            }
#pragma unroll
            for (int mt = 0; mt < 4; mt++)
#pragma unroll
                for (int nt = 0; nt < 8; nt++) {
                    const int bo_ = (nt >> 1) * 4 + (nt & 1) * 2;
                    MMA16816(acc[mt][nt], &ah[mt * 4], bh[bo_], bh[bo_ + 1]);
                }
        }
        if (donx) CP_COMMIT();

        // ---- tile end: dequantize -> int8 store + per-row qmin ----
        if (ccc == CHUNKS - 1) {
            int qmn[8];
#pragma unroll
            for (int sl = 0; sl < 8; sl++) qmn[sl] = 127;
#pragma unroll
            for (int nt = 0; nt < 8; nt++) {
                int cb = colBase + cct * BN + wc * 64 + nt * 8 + (lane & 3) * 2;
                float e0 = __ldg(&g_enorm[cb]);
                float e1 = __ldg(&g_enorm[cb + 1]);
#pragma unroll
                for (int mt = 0; mt < 4; mt++)
#pragma unroll
                    for (int h = 0; h < 2; h++) {
                        const int sl = mt * 2 + h;
                        float d0 = acc[mt][nt][h * 2], d1 = acc[mt][nt][h * 2 + 1];
                        int q0 = __float2int_rn(fminf(fmaxf((e0 - 2.0f * d0) * QS8, -128.f), 127.f));
                        int q1 = __float2int_rn(fminf(fmaxf((e1 - 2.0f * d1) * QS8, -128.f), 127.f));
                        int row0 = rowBase + wr * 64 + mt * 16 + h * 8 + (lane >> 2);
                        *(char2*)&g_s8[(size_t)row0 * KC + cb] =
                            make_char2((signed char)q0, (signed char)q1);
                        qmn[sl] = min(qmn[sl], min(q0, q1));
                        acc[mt][nt][h * 2] = 0.f;
                        acc[mt][nt][h * 2 + 1] = 0.f;
                    }
            }
#pragma unroll
            for (int off = 1; off <= 2; off <<= 1)
#pragma unroll
                for (int sl = 0; sl < 8; sl++)
                    qmn[sl] = min(qmn[sl], __shfl_xor_sync(0xffffffffu, qmn[sl], off));
            if ((lane & 3) == 0) {
#pragma unroll
                for (int sl = 0; sl < 8; sl++) {
                    int row0 = rowBase + wr * 64 + (sl >> 1) * 16 + (sl & 1) * 8 + (lane >> 2);
                    atomicMin(&g_qmin[row0], qmn[sl]);
                }
            }
        }
        if (++ccc == CHUNKS) { ccc = 0; ++cct; }
    }
}

// -------- refine: int8 candidate scan + exact argmin + gather + loss --------
__global__ __launch_bounds__(256)
void refine_kernel(const float* __restrict__ z, const float* __restrict__ emb,
                   float* __restrict__ ids_out, float* __restrict__ zq) {
    __shared__ float redl[8];
    const int w    = threadIdx.x >> 5;
    const int lane = threadIdx.x & 31;
    const int r    = blockIdx.x * 8 + w;

    const float zr = g_zsum[r];
    const int qthr = min(g_qmin[r] + QWIN8, 127);
    const int thr4 = (qthr & 0xFF) * 0x01010101;

    // z row in registers (exact fp32)
    float zreg[24];
    const float* zrow = z + (size_t)r * DIM;
#pragma unroll
    for (int j = 0; j < 24; j++) zreg[j] = zrow[lane + j * 32];

    // single pass over int8 scores: packed byte pre-test, then extract
    const int2* q2 = (const int2*)(g_s8 + (size_t)r * KC);
    int cand[8];
    int nc = 0;
#pragma unroll
    for (int j = 0; j < 8; j++) {
        int2 v = q2[lane + j * 32];
        int base = (lane + j * 32) * 8;
        unsigned mx = __vcmples4((unsigned)v.x, (unsigned)thr4);
        unsigned my = __vcmples4((unsigned)v.y, (unsigned)thr4);
        if (mx) {
#pragma unroll
            for (int b = 0; b < 4; b++)
                if ((mx >> (8 * b)) & 0xFF) { if (nc < 8) cand[nc++] = base + b; }
        }
        if (my) {
#pragma unroll
            for (int b = 0; b < 4; b++)
                if ((my >> (8 * b)) & 0xFF) { if (nc < 8) cand[nc++] = base + 4 + b; }
        }
    }

    // warp-cooperative exact rescore (reference rounding, first-index ties)
    float best = 3.4e38f;
    int   bi   = INT_MAX;
    unsigned m = __ballot_sync(0xffffffffu, nc > 0);
    while (m) {
        int l = __ffs(m) - 1;
        m &= m - 1;
        int cnt = __shfl_sync(0xffffffffu, nc, l);
        for (int t = 0; t < cnt; t++) {
            int cc = __shfl_sync(0xffffffffu, cand[t], l);
            const float* erow = emb + (size_t)cc * DIM;
            float d = 0.f;
#pragma unroll
            for (int j = 0; j < 24; j++) d = fmaf(zreg[j], erow[lane + j * 32], d);
#pragma unroll
            for (int o = 16; o > 0; o >>= 1) d += __shfl_xor_sync(0xffffffffu, d, o);
            float se = (zr + g_enorm[cc]) - 2.0f * d;   // fl(fl(zsum+enorm)-2*dot)
            if (se < best || (se == best && cc < bi)) { best = se; bi = cc; }
        }
    }

    // gather z_q + commitment-loss partial
    const float* erow = emb + (size_t)bi * DIM;
    float* qrow = zq + (size_t)r * DIM;
    float lacc = 0.f;
#pragma unroll
    for (int j = 0; j < 24; j++) {
        float q = erow[lane + j * 32];
        qrow[lane + j * 32] = q;
        float dd = zreg[j] - q;
        lacc = fmaf(dd, dd, lacc);
    }
#pragma unroll
    for (int o = 16; o > 0; o >>= 1) lacc += __shfl_down_sync(0xffffffffu, lacc, o);
    if (lane == 0) {
        ids_out[r] = (float)bi;
        redl[w] = lacc;
    }
    __syncthreads();
    if (threadIdx.x == 0) {
        float t = 0.f;
#pragma unroll
        for (int i = 0; i < 8; i++) t += redl[i];
        atomicAdd(&g_loss, t);
    }
}

__global__ void finalize_kernel(float* __restrict__ loss_out) {
    *loss_out = 0.25f * (g_loss / (float)((long long)NROWS * DIM));
}

// ---------------- launch ----------------
extern "C" void kernel_launch(void* const* d_in, const int* in_sizes, int n_in,
                              void* d_out, int out_size) {
    (void)in_sizes; (void)n_in; (void)out_size;
    const float* z   = (const float*)d_in[0];
    const float* emb = (const float*)d_in[1];
    float* out   = (float*)d_out;
    float* zq    = out;                              // [NROWS*DIM]
    float* idsf  = out + (size_t)NROWS * DIM;        // [NROWS]
    float* lossp = idsf + NROWS;                     // [1]

    __nv_bfloat16 *zhi_p, *ehi_p;
    float *zsum_p, *enorm_p;
    cudaGetSymbolAddress((void**)&zhi_p, g_zhi);
    cudaGetSymbolAddress((void**)&ehi_p, g_ehi);
    cudaGetSymbolAddress((void**)&zsum_p, g_zsum);
    cudaGetSymbolAddress((void**)&enorm_p, g_enorm);

    const int VQ_SMEM = 3 * STAGE + 128;            // 98432 (x2 CTAs = 192KB/SM)
    cudaFuncSetAttribute(vq_pass1_kernel, cudaFuncAttributeMaxDynamicSharedMemorySize, VQ_SMEM);

    prep_kernel<<<NROWS / 8, 256>>>(z, zhi_p, zsum_p, NROWS);
    prep_kernel<<<KC / 8, 256>>>(emb, ehi_p, enorm_p, KC);
    vq_pass1_kernel<<<(NROWS / BM) * 2, 128, VQ_SMEM>>>();
    refine_kernel<<<NROWS / 8, 256>>>(z, emb, idsf, zq);
    finalize_kernel<<<1, 1>>>(lossp);
}

// round 13
// speedup vs baseline: 1.1145x; 1.1145x over previous
#include <cuda_runtime.h>
#include <cuda_bf16.h>
#include <cstdint>
#include <climits>

#define DIM    768
#define KC     2048
#define NROWS  16384
#define BM     128               // rows per CTA
#define BNH    1024              // codes per CTA (half the codebook)
#define BN     128               // codes per tile iteration
#define BK     64                // bf16 elems per chunk = 128 B/row
#define CHUNKS (DIM / BK)        // 12
#define NTILE  (BNH / BN)        // 8
#define TOT    (NTILE * BK ? (NTILE * CHUNKS) : 0)  // 96
#define STAGE  32768             // A 16KB + B 16KB
#define QSCALE 131072.0f
#define QTHR_Q 85                // refine window in quanta (~6.5e-4)

__device__ float g_enorm[KC];
__device__ float g_zsum[NROWS];
__device__ float g_loss;
__device__ int   g_qmin[NROWS];
__device__ __nv_bfloat16 g_zhi[(size_t)NROWS * DIM];
__device__ __nv_bfloat16 g_ehi[(size_t)KC * DIM];
__device__ short g_si[(size_t)NROWS * KC];     // 64 MiB quantized scores

static __device__ __forceinline__ uint32_t smem_u32(const void* p) {
    uint32_t a;
    asm("{ .reg .u64 t; cvta.to.shared.u64 t, %1; cvt.u32.u64 %0, t; }" : "=r"(a) : "l"(p));
    return a;
}
#define CP_ASYNC16(dst, src) \
    asm volatile("cp.async.cg.shared.global [%0], [%1], 16;" :: "r"(dst), "l"(src))
#define CP_COMMIT() asm volatile("cp.async.commit_group;" ::: "memory")
#define LDMX4(r, addr) \
    asm volatile("ldmatrix.sync.aligned.m8n8.x4.shared.b16 {%0,%1,%2,%3}, [%4];" \
        : "=r"((r)[0]), "=r"((r)[1]), "=r"((r)[2]), "=r"((r)[3]) : "r"(addr))
#define MMA16816(d, a, b0_, b1_) \
    asm volatile("mma.sync.aligned.m16n8k16.row.col.f32.bf16.bf16.f32 " \
        "{%0,%1,%2,%3}, {%4,%5,%6,%7}, {%8,%9}, {%0,%1,%2,%3};" \
        : "+f"((d)[0]), "+f"((d)[1]), "+f"((d)[2]), "+f"((d)[3]) \
        : "r"((a)[0]), "r"((a)[1]), "r"((a)[2]), "r"((a)[3]), "r"(b0_), "r"(b1_))

// -------- fused fp32->bf16 convert + row norm + qmin/loss init (warp/row) --------
__global__ void prep_kernel(const float* __restrict__ src,
                            __nv_bfloat16* __restrict__ dst,
                            float* __restrict__ norms, int nrows) {
    int w    = (blockIdx.x * blockDim.x + threadIdx.x) >> 5;
    int lane = threadIdx.x & 31;
    if (w >= nrows) return;
    const float2* s2 = (const float2*)(src + (size_t)w * DIM);
    __nv_bfloat162* d2 = (__nv_bfloat162*)(dst + (size_t)w * DIM);
    float acc = 0.f;
#pragma unroll
    for (int j = 0; j < DIM / 64; j++) {
        float2 v = s2[lane + j * 32];
        acc = fmaf(v.x, v.x, fmaf(v.y, v.y, acc));
        d2[lane + j * 32] = __halves2bfloat162(__float2bfloat16_rn(v.x),
                                               __float2bfloat16_rn(v.y));
    }
#pragma unroll
    for (int o = 16; o > 0; o >>= 1) acc += __shfl_down_sync(0xffffffffu, acc, o);
    if (lane == 0) {
        norms[w] = acc;
        g_qmin[w] = INT_MAX;        // idempotent init (runs in both prep launches)
        if (w == 0) g_loss = 0.f;
    }
}

// -------- pass 1: bf16 HMMA approx GEMM -> int16 scores + per-row qmin --------
// 256 CTAs x 128 thr (2 CTAs/SM). CTA: 128 rows x 1024 codes.
// 4 warps 2x2, warp tile 64x64. 2-stage ring; cp.async in the MMA shadow;
// A fragments software-pipelined one ks-step ahead (double-buffered).
__global__ __launch_bounds__(128, 2)
void vq_pass1_kernel() {
    extern __shared__ char smem_raw[];
    const uint32_t sb = (smem_u32(smem_raw) + 127u) & ~127u;
    const int tid  = threadIdx.x;
    const int lane = tid & 31;
    const int w    = tid >> 5;
    const int wr   = w >> 1;    // 0..1  rows 64 each
    const int wc   = w & 1;     // 0..1  cols 64 each
    const int rowBase = (blockIdx.x >> 1) * BM;
    const int colBase = (blockIdx.x & 1) * BNH;

    // ---- cp.async addressing: 16 x 16B per thread per stage ----
    const int gr  = tid >> 3;          // base row 0..15
    const int gg  = tid & 7;           // granule 0..7
    const uint32_t swx = (uint32_t)((gg ^ (gr & 7)) << 4);
    const uint32_t da  = (uint32_t)(gr * 128) + swx;            // A dst base
    const uint32_t db  = 16384u + (uint32_t)(gr * 128) + swx;   // B dst base
    const __nv_bfloat16* baseA = g_zhi + (size_t)(rowBase + gr) * DIM + gg * 8;
    const __nv_bfloat16* baseB = g_ehi + (size_t)(colBase + gr) * DIM + gg * 8;

    // ---- ldmatrix lane addressing ----
    const int arow = lane & 15;
    const int agr  = lane >> 4;
    const int brow = (lane & 7) + ((lane >> 4) & 1) * 8;
    const int bgr  = (lane >> 3) & 1;
    uint32_t a_rt[4]; int a_sw[4];
#pragma unroll
    for (int mt = 0; mt < 4; mt++) {
        int r = wr * 64 + mt * 16 + arow;
        a_rt[mt] = r * 128; a_sw[mt] = r & 7;
    }
    uint32_t b_rt[4]; int b_sw[4];
#pragma unroll
    for (int nb = 0; nb < 4; nb++) {
        int r = wc * 64 + nb * 16 + brow;
        b_rt[nb] = r * 128; b_sw[nb] = r & 7;
    }

    float acc[4][8][4];
#pragma unroll
    for (int mt = 0; mt < 4; mt++)
#pragma unroll
        for (int nt = 0; nt < 8; nt++)
#pragma unroll
            for (int q = 0; q < 4; q++) acc[mt][nt][q] = 0.f;

    auto issue_all = [&](int ct, int c, int buf) {
        const uint32_t st = sb + (uint32_t)buf * STAGE;
        const __nv_bfloat16* pa = baseA + c * BK;
#pragma unroll
        for (int k = 0; k < 8; k++)
            CP_ASYNC16(st + da + (uint32_t)k * 2048u, pa + (size_t)k * 16 * DIM);
        const __nv_bfloat16* pb = baseB + (size_t)ct * BN * DIM + c * BK;
#pragma unroll
        for (int k = 0; k < 8; k++)
            CP_ASYNC16(st + db + (uint32_t)k * 2048u, pb + (size_t)k * 16 * DIM);
        CP_COMMIT();
    };

    issue_all(0, 0, 0);
    int cct = 0, ccc = 0;

    for (int s = 0; s < TOT; s++) {
        asm volatile("cp.async.wait_group 0;" ::: "memory");
        __syncthreads();

        const int nx    = s + 1;
        const bool donx = nx < TOT;
        const uint32_t nst = sb + (uint32_t)(nx & 1) * STAGE;
        const __nv_bfloat16* npa = baseA + (nx % CHUNKS) * BK;
        const __nv_bfloat16* npb = baseB + (size_t)(nx / CHUNKS) * BN * DIM + (nx % CHUNKS) * BK;

        const uint32_t Ab = sb + (uint32_t)(s & 1) * STAGE;
        const uint32_t Bb = Ab + 16384u;

        // A fragments double-buffered across ks-steps
        uint32_t ah[2][16];
#pragma unroll
        for (int mt = 0; mt < 4; mt++) {    // prefetch ks=0 A
            uint32_t ad = Ab + a_rt[mt] + (uint32_t)((agr ^ a_sw[mt]) << 4);
            LDMX4(&ah[0][mt * 4], ad);
        }

#pragma unroll
        for (int ks = 0; ks < 4; ks++) {
            const int g0 = ks * 2;
            const int cur = ks & 1, nxt = cur ^ 1;
            uint32_t bh[16];
#pragma unroll
            for (int nb = 0; nb < 4; nb++) {
                uint32_t bd = Bb + b_rt[nb] + (uint32_t)(((g0 + bgr) ^ b_sw[nb]) << 4);
                LDMX4(&bh[nb * 4], bd);
            }
            // prefetch next ks-step's A fragments (retire in this step's MMA shadow)
            if (ks < 3) {
#pragma unroll
                for (int mt = 0; mt < 4; mt++) {
                    uint32_t ad = Ab + a_rt[mt] + (uint32_t)(((g0 + 2 + agr) ^ a_sw[mt]) << 4);
                    LDMX4(&ah[nxt][mt * 4], ad);
                }
            }
            // cp.async issue in the LDSM->MMA dependency shadow (4 per ks)
            if (donx) {
                if (ks < 2) {
#pragma unroll
                    for (int k = ks * 4; k < ks * 4 + 4; k++)
                        CP_ASYNC16(nst + da + (uint32_t)k * 2048u, npa + (size_t)k * 16 * DIM);
                } else {
#pragma unroll
                    for (int k = (ks - 2) * 4; k < (ks - 2) * 4 + 4; k++)
                        CP_ASYNC16(nst + db + (uint32_t)k * 2048u, npb + (size_t)k * 16 * DIM);
                }
            }
#pragma unroll
            for (int mt = 0; mt < 4; mt++)
#pragma unroll
                for (int nt = 0; nt < 8; nt++) {
                    const int bo_ = (nt >> 1) * 4 + (nt & 1) * 2;
                    MMA16816(acc[mt][nt], &ah[cur][mt * 4], bh[bo_], bh[bo_ + 1]);
                }
        }
        if (donx) CP_COMMIT();

        // ---- tile end: dequantize -> int16 store + per-row qmin ----
        if (ccc == CHUNKS - 1) {
            int qmn[8];
#pragma unroll
            for (int sl = 0; sl < 8; sl++) qmn[sl] = 32767;
#pragma unroll
            for (int nt = 0; nt < 8; nt++) {
                int cb = colBase + cct * BN + wc * 64 + nt * 8 + (lane & 3) * 2;
                float e0 = __ldg(&g_enorm[cb]);
                float e1 = __ldg(&g_enorm[cb + 1]);
#pragma unroll
                for (int mt = 0; mt < 4; mt++)
#pragma unroll
                    for (int h = 0; h < 2; h++) {
                        const int sl = mt * 2 + h;
                        float d0 = acc[mt][nt][h * 2], d1 = acc[mt][nt][h * 2 + 1];
                        int q0 = __float2int_rn(fminf(fmaxf((e0 - 2.0f * d0) * QSCALE, -32767.f), 32767.f));
                        int q1 = __float2int_rn(fminf(fmaxf((e1 - 2.0f * d1) * QSCALE, -32767.f), 32767.f));
                        int row0 = rowBase + wr * 64 + mt * 16 + h * 8 + (lane >> 2);
                        *(short2*)&g_si[(size_t)row0 * KC + cb] =
                            make_short2((short)q0, (short)q1);
                        qmn[sl] = min(qmn[sl], min(q0, q1));
                        acc[mt][nt][h * 2] = 0.f;
                        acc[mt][nt][h * 2 + 1] = 0.f;
                    }
            }
#pragma unroll
            for (int off = 1; off <= 2; off <<= 1)
#pragma unroll
                for (int sl = 0; sl < 8; sl++)
                    qmn[sl] = min(qmn[sl], __shfl_xor_sync(0xffffffffu, qmn[sl], off));
            if ((lane & 3) == 0) {
#pragma unroll
                for (int sl = 0; sl < 8; sl++) {
                    int row0 = rowBase + wr * 64 + (sl >> 1) * 16 + (sl & 1) * 8 + (lane >> 2);
                    atomicMin(&g_qmin[row0], qmn[sl]);
                }
            }
        }
        if (++ccc == CHUNKS) { ccc = 0; ++cct; }
    }
}

// -------- refine: single-pass candidate scan + exact argmin + gather + loss --------
__global__ __launch_bounds__(256)
void refine_kernel(const float* __restrict__ z, const float* __restrict__ emb,
                   float* __restrict__ ids_out, float* __restrict__ zq) {
    __shared__ float redl[8];
    const int w    = threadIdx.x >> 5;
    const int lane = threadIdx.x & 31;
    const int r    = blockIdx.x * 8 + w;

    const float zr = g_zsum[r];
    const int qthr = g_qmin[r] + QTHR_Q;

    // z row in registers (exact fp32)
    float zreg[24];
    const float* zrow = z + (size_t)r * DIM;
#pragma unroll
    for (int j = 0; j < 24; j++) zreg[j] = zrow[lane + j * 32];

    // single pass: collect candidates locally (avg ~1 per row over the warp)
    const short2* q2 = (const short2*)(g_si + (size_t)r * KC);
    int cand[4];
    int nc = 0;
#pragma unroll 8
    for (int j = 0; j < 32; j++) {
        short2 p = q2[lane + j * 32];
        int base = (lane + j * 32) * 2;
        if ((int)p.x <= qthr && nc < 4) cand[nc++] = base;
        if ((int)p.y <= qthr && nc < 4) cand[nc++] = base + 1;
    }

    // warp-cooperative exact rescore (reference rounding, first-index ties)
    float best = 3.4e38f;
    int   bi   = INT_MAX;
    unsigned m = __ballot_sync(0xffffffffu, nc > 0);
    while (m) {
        int l = __ffs(m) - 1;
        m &= m - 1;
        int cnt = __shfl_sync(0xffffffffu, nc, l);
        for (int t = 0; t < cnt; t++) {
            int cc = __shfl_sync(0xffffffffu, cand[t], l);
            const float* erow = emb + (size_t)cc * DIM;
            float d = 0.f;
#pragma unroll
            for (int j = 0; j < 24; j++) d = fmaf(zreg[j], erow[lane + j * 32], d);
#pragma unroll
            for (int o = 16; o > 0; o >>= 1) d += __shfl_xor_sync(0xffffffffu, d, o);
            float se = (zr + g_enorm[cc]) - 2.0f * d;   // fl(fl(zsum+enorm)-2*dot)
            if (se < best || (se == best && cc < bi)) { best = se; bi = cc; }
        }
    }

    // gather z_q + commitment-loss partial
    const float* erow = emb + (size_t)bi * DIM;
    float* qrow = zq + (size_t)r * DIM;
    float lacc = 0.f;
#pragma unroll
    for (int j = 0; j < 24; j++) {
        float q = erow[lane + j * 32];
        qrow[lane + j * 32] = q;
        float dd = zreg[j] - q;
        lacc = fmaf(dd, dd, lacc);
    }
#pragma unroll
    for (int o = 16; o > 0; o >>= 1) lacc += __shfl_down_sync(0xffffffffu, lacc, o);
    if (lane == 0) {
        ids_out[r] = (float)bi;
        redl[w] = lacc;
    }
    __syncthreads();
    if (threadIdx.x == 0) {
        float t = 0.f;
#pragma unroll
        for (int i = 0; i < 8; i++) t += redl[i];
        atomicAdd(&g_loss, t);
    }
}

__global__ void finalize_kernel(float* __restrict__ loss_out) {
    *loss_out = 0.25f * (g_loss / (float)((long long)NROWS * DIM));
}

// ---------------- launch ----------------
extern "C" void kernel_launch(void* const* d_in, const int* in_sizes, int n_in,
                              void* d_out, int out_size) {
    (void)in_sizes; (void)n_in; (void)out_size;
    const float* z   = (const float*)d_in[0];
    const float* emb = (const float*)d_in[1];
    float* out   = (float*)d_out;
    float* zq    = out;                              // [NROWS*DIM]
    float* idsf  = out + (size_t)NROWS * DIM;        // [NROWS]
    float* lossp = idsf + NROWS;                     // [1]

    __nv_bfloat16 *zhi_p, *ehi_p;
    float *zsum_p, *enorm_p;
    cudaGetSymbolAddress((void**)&zhi_p, g_zhi);
    cudaGetSymbolAddress((void**)&ehi_p, g_ehi);
    cudaGetSymbolAddress((void**)&zsum_p, g_zsum);
    cudaGetSymbolAddress((void**)&enorm_p, g_enorm);

    const int VQ_SMEM = 2 * STAGE + 128;            // 65664
    cudaFuncSetAttribute(vq_pass1_kernel, cudaFuncAttributeMaxDynamicSharedMemorySize, VQ_SMEM);

    prep_kernel<<<NROWS / 8, 256>>>(z, zhi_p, zsum_p, NROWS);
    prep_kernel<<<KC / 8, 256>>>(emb, ehi_p, enorm_p, KC);
    vq_pass1_kernel<<<(NROWS / BM) * 2, 128, VQ_SMEM>>>();
    refine_kernel<<<NROWS / 8, 256>>>(z, emb, idsf, zq);
    finalize_kernel<<<1, 1>>>(lossp);
}

// round 14
// speedup vs baseline: 1.1997x; 1.0764x over previous
#include <cuda_runtime.h>
#include <cuda_bf16.h>
#include <cstdint>
#include <climits>

#define DIM    768
#define KC     2048
#define NROWS  16384
#define BM     128               // rows per unit
#define BN     128               // codes per unit
#define BK     64                // bf16 elems per chunk = 128 B/row
#define CHUNKS (DIM / BK)        // 12
#define NUNITS ((NROWS / BM) * (KC / BN))  // 2048
#define NCTA   296               // 2 CTAs per SM exactly
#define STAGE  32768             // A 16KB + B 16KB
#define QSCALE 131072.0f
#define QTHR_Q 85                // refine window in quanta (~6.5e-4)

__device__ float g_enorm[KC];
__device__ float g_zsum[NROWS];
__device__ float g_loss;
__device__ int   g_qmin[NROWS];
__device__ __nv_bfloat16 g_zhi[(size_t)NROWS * DIM];
__device__ __nv_bfloat16 g_ehi[(size_t)KC * DIM];
__device__ short g_si[(size_t)NROWS * KC];     // 64 MiB quantized scores

static __device__ __forceinline__ uint32_t smem_u32(const void* p) {
    uint32_t a;
    asm("{ .reg .u64 t; cvta.to.shared.u64 t, %1; cvt.u32.u64 %0, t; }" : "=r"(a) : "l"(p));
    return a;
}
#define CP_ASYNC16(dst, src) \
    asm volatile("cp.async.cg.shared.global [%0], [%1], 16;" :: "r"(dst), "l"(src))
#define CP_COMMIT() asm volatile("cp.async.commit_group;" ::: "memory")
#define LDMX4(r, addr) \
    asm volatile("ldmatrix.sync.aligned.m8n8.x4.shared.b16 {%0,%1,%2,%3}, [%4];" \
        : "=r"((r)[0]), "=r"((r)[1]), "=r"((r)[2]), "=r"((r)[3]) : "r"(addr))
#define MMA16816(d, a, b0_, b1_) \
    asm volatile("mma.sync.aligned.m16n8k16.row.col.f32.bf16.bf16.f32 " \
        "{%0,%1,%2,%3}, {%4,%5,%6,%7}, {%8,%9}, {%0,%1,%2,%3};" \
        : "+f"((d)[0]), "+f"((d)[1]), "+f"((d)[2]), "+f"((d)[3]) \
        : "r"((a)[0]), "r"((a)[1]), "r"((a)[2]), "r"((a)[3]), "r"(b0_), "r"(b1_))

// -------- fused fp32->bf16 convert + row norm + qmin/loss init (warp/row) --------
__global__ void prep_kernel(const float* __restrict__ src,
                            __nv_bfloat16* __restrict__ dst,
                            float* __restrict__ norms, int nrows) {
    int w    = (blockIdx.x * blockDim.x + threadIdx.x) >> 5;
    int lane = threadIdx.x & 31;
    if (w >= nrows) return;
    const float2* s2 = (const float2*)(src + (size_t)w * DIM);
    __nv_bfloat162* d2 = (__nv_bfloat162*)(dst + (size_t)w * DIM);
    float acc = 0.f;
#pragma unroll
    for (int j = 0; j < DIM / 64; j++) {
        float2 v = s2[lane + j * 32];
        acc = fmaf(v.x, v.x, fmaf(v.y, v.y, acc));
        d2[lane + j * 32] = __halves2bfloat162(__float2bfloat16_rn(v.x),
                                               __float2bfloat16_rn(v.y));
    }
#pragma unroll
    for (int o = 16; o > 0; o >>= 1) acc += __shfl_down_sync(0xffffffffu, acc, o);
    if (lane == 0) {
        norms[w] = acc;
        g_qmin[w] = INT_MAX;        // idempotent init (runs in both prep launches)
        if (w == 0) g_loss = 0.f;
    }
}

// -------- pass 1: persistent bf16 HMMA GEMM -> int16 scores + per-row qmin --------
// 296 persistent CTAs x 128 thr (exactly 2/SM). Unit = 128 rows x 128 codes,
// 12 K-chunk iterations. CTA b handles units b, b+296, ... Pipeline runs
// seamlessly across unit boundaries (shadow prefetch of next (unit,chunk)).
__global__ __launch_bounds__(128, 2)
void vq_pass1_kernel() {
    extern __shared__ char smem_raw[];
    const uint32_t sb = (smem_u32(smem_raw) + 127u) & ~127u;
    const int tid  = threadIdx.x;
    const int lane = tid & 31;
    const int w    = tid >> 5;
    const int wr   = w >> 1;    // 0..1  rows 64 each
    const int wc   = w & 1;     // 0..1  cols 64 each

    // ---- cp.async addressing: 16 x 16B per thread per stage ----
    const int gr  = tid >> 3;          // base row 0..15
    const int gg  = tid & 7;           // granule 0..7
    const uint32_t swx = (uint32_t)((gg ^ (gr & 7)) << 4);
    const uint32_t da  = (uint32_t)(gr * 128) + swx;            // A dst base
    const uint32_t db  = 16384u + (uint32_t)(gr * 128) + swx;   // B dst base
    const size_t aoff = (size_t)gr * DIM + gg * 8;

    // ---- ldmatrix lane addressing ----
    const int arow = lane & 15;
    const int agr  = lane >> 4;
    const int brow = (lane & 7) + ((lane >> 4) & 1) * 8;
    const int bgr  = (lane >> 3) & 1;
    uint32_t a_rt[4]; int a_sw[4];
#pragma unroll
    for (int mt = 0; mt < 4; mt++) {
        int r = wr * 64 + mt * 16 + arow;
        a_rt[mt] = r * 128; a_sw[mt] = r & 7;
    }
    uint32_t b_rt[4]; int b_sw[4];
#pragma unroll
    for (int nb = 0; nb < 4; nb++) {
        int r = wc * 64 + nb * 16 + brow;
        b_rt[nb] = r * 128; b_sw[nb] = r & 7;
    }

    float acc[4][8][4];
#pragma unroll
    for (int mt = 0; mt < 4; mt++)
#pragma unroll
        for (int nt = 0; nt < 8; nt++)
#pragma unroll
            for (int q = 0; q < 4; q++) acc[mt][nt][q] = 0.f;

    // prologue: issue (unit=blockIdx.x, chunk=0) into buf 0
    {
        const __nv_bfloat16* pa = g_zhi + (size_t)(blockIdx.x >> 4) * BM * DIM + aoff;
        const __nv_bfloat16* pb = g_ehi + (size_t)(blockIdx.x & 15) * BN * DIM + aoff;
#pragma unroll
        for (int k = 0; k < 8; k++)
            CP_ASYNC16(sb + da + (uint32_t)k * 2048u, pa + (size_t)k * 16 * DIM);
#pragma unroll
        for (int k = 0; k < 8; k++)
            CP_ASYNC16(sb + db + (uint32_t)k * 2048u, pb + (size_t)k * 16 * DIM);
        CP_COMMIT();
    }

    int cu = blockIdx.x, cc = 0;   // compute unit/chunk
    int pu = blockIdx.x, pc = 0;   // last-issued unit/chunk
    int it = 0;

    while (cu < NUNITS) {
        asm volatile("cp.async.wait_group 0;" ::: "memory");
        __syncthreads();

        // advance prefetch state to the next (unit, chunk)
        if (++pc == CHUNKS) { pc = 0; pu += NCTA; }
        const bool donx = pu < NUNITS;
        const uint32_t nst = sb + (uint32_t)((it + 1) & 1) * STAGE;
        const __nv_bfloat16* npa = g_zhi + (size_t)(pu >> 4) * BM * DIM + aoff + pc * BK;
        const __nv_bfloat16* npb = g_ehi + (size_t)(pu & 15) * BN * DIM + aoff + pc * BK;

        const uint32_t Ab = sb + (uint32_t)(it & 1) * STAGE;
        const uint32_t Bb = Ab + 16384u;

        // A fragments double-buffered across ks-steps
        uint32_t ah[2][16];
#pragma unroll
        for (int mt = 0; mt < 4; mt++) {    // prefetch ks=0 A
            uint32_t ad = Ab + a_rt[mt] + (uint32_t)((agr ^ a_sw[mt]) << 4);
            LDMX4(&ah[0][mt * 4], ad);
        }

#pragma unroll
        for (int ks = 0; ks < 4; ks++) {
            const int g0 = ks * 2;
            const int cur = ks & 1, nxt = cur ^ 1;
            uint32_t bh[16];
#pragma unroll
            for (int nb = 0; nb < 4; nb++) {
                uint32_t bd = Bb + b_rt[nb] + (uint32_t)(((g0 + bgr) ^ b_sw[nb]) << 4);
                LDMX4(&bh[nb * 4], bd);
            }
            if (ks < 3) {
#pragma unroll
                for (int mt = 0; mt < 4; mt++) {
                    uint32_t ad = Ab + a_rt[mt] + (uint32_t)(((g0 + 2 + agr) ^ a_sw[mt]) << 4);
                    LDMX4(&ah[nxt][mt * 4], ad);
                }
            }
            // cp.async issue in the LDSM->MMA dependency shadow (4 per ks)
            if (donx) {
                if (ks < 2) {
#pragma unroll
                    for (int k = ks * 4; k < ks * 4 + 4; k++)
                        CP_ASYNC16(nst + da + (uint32_t)k * 2048u, npa + (size_t)k * 16 * DIM);
                } else {
#pragma unroll
                    for (int k = (ks - 2) * 4; k < (ks - 2) * 4 + 4; k++)
                        CP_ASYNC16(nst + db + (uint32_t)k * 2048u, npb + (size_t)k * 16 * DIM);
                }
            }
#pragma unroll
            for (int mt = 0; mt < 4; mt++)
#pragma unroll
                for (int nt = 0; nt < 8; nt++) {
                    const int bo_ = (nt >> 1) * 4 + (nt & 1) * 2;
                    MMA16816(acc[mt][nt], &ah[cur][mt * 4], bh[bo_], bh[bo_ + 1]);
                }
        }
        if (donx) CP_COMMIT();

        // ---- unit end: dequantize -> int16 store + per-row qmin ----
        if (cc == CHUNKS - 1) {
            const int rowB = (cu >> 4) * BM;
            const int colB = (cu & 15) * BN;
            int qmn[8];
#pragma unroll
            for (int sl = 0; sl < 8; sl++) qmn[sl] = 32767;
#pragma unroll
            for (int nt = 0; nt < 8; nt++) {
                int cb = colB + wc * 64 + nt * 8 + (lane & 3) * 2;
                float e0 = __ldg(&g_enorm[cb]);
                float e1 = __ldg(&g_enorm[cb + 1]);
#pragma unroll
                for (int mt = 0; mt < 4; mt++)
#pragma unroll
                    for (int h = 0; h < 2; h++) {
                        const int sl = mt * 2 + h;
                        float d0 = acc[mt][nt][h * 2], d1 = acc[mt][nt][h * 2 + 1];
                        int q0 = __float2int_rn(fminf(fmaxf((e0 - 2.0f * d0) * QSCALE, -32767.f), 32767.f));
                        int q1 = __float2int_rn(fminf(fmaxf((e1 - 2.0f * d1) * QSCALE, -32767.f), 32767.f));
                        int row0 = rowB + wr * 64 + mt * 16 + h * 8 + (lane >> 2);
                        *(short2*)&g_si[(size_t)row0 * KC + cb] =
                            make_short2((short)q0, (short)q1);
                        qmn[sl] = min(qmn[sl], min(q0, q1));
                        acc[mt][nt][h * 2] = 0.f;
                        acc[mt][nt][h * 2 + 1] = 0.f;
                    }
            }
#pragma unroll
            for (int off = 1; off <= 2; off <<= 1)
#pragma unroll
                for (int sl = 0; sl < 8; sl++)
                    qmn[sl] = min(qmn[sl], __shfl_xor_sync(0xffffffffu, qmn[sl], off));
            if ((lane & 3) == 0) {
#pragma unroll
                for (int sl = 0; sl < 8; sl++) {
                    int row0 = rowB + wr * 64 + (sl >> 1) * 16 + (sl & 1) * 8 + (lane >> 2);
                    atomicMin(&g_qmin[row0], qmn[sl]);
                }
            }
        }
        if (++cc == CHUNKS) { cc = 0; cu += NCTA; }
        ++it;
    }
}

// -------- refine: single-pass candidate scan + exact argmin + gather + loss --------
__global__ __launch_bounds__(256)
void refine_kernel(const float* __restrict__ z, const float* __restrict__ emb,
                   float* __restrict__ ids_out, float* __restrict__ zq) {
    __shared__ float redl[8];
    const int w    = threadIdx.x >> 5;
    const int lane = threadIdx.x & 31;
    const int r    = blockIdx.x * 8 + w;

    const float zr = g_zsum[r];
    const int qthr = g_qmin[r] + QTHR_Q;

    // z row in registers (exact fp32)
    float zreg[24];
    const float* zrow = z + (size_t)r * DIM;
#pragma unroll
    for (int j = 0; j < 24; j++) zreg[j] = zrow[lane + j * 32];

    // single pass: collect candidates locally (avg ~1 per row over the warp)
    const short2* q2 = (const short2*)(g_si + (size_t)r * KC);
    int cand[4];
    int nc = 0;
#pragma unroll 8
    for (int j = 0; j < 32; j++) {
        short2 p = q2[lane + j * 32];
        int base = (lane + j * 32) * 2;
        if ((int)p.x <= qthr && nc < 4) cand[nc++] = base;
        if ((int)p.y <= qthr && nc < 4) cand[nc++] = base + 1;
    }

    // warp-cooperative exact rescore (reference rounding, first-index ties)
    float best = 3.4e38f;
    int   bi   = INT_MAX;
    unsigned m = __ballot_sync(0xffffffffu, nc > 0);
    while (m) {
        int l = __ffs(m) - 1;
        m &= m - 1;
        int cnt = __shfl_sync(0xffffffffu, nc, l);
        for (int t = 0; t < cnt; t++) {
            int cc = __shfl_sync(0xffffffffu, cand[t], l);
            const float* erow = emb + (size_t)cc * DIM;
            float d = 0.f;
#pragma unroll
            for (int j = 0; j < 24; j++) d = fmaf(zreg[j], erow[lane + j * 32], d);
#pragma unroll
            for (int o = 16; o > 0; o >>= 1) d += __shfl_xor_sync(0xffffffffu, d, o);
            float se = (zr + g_enorm[cc]) - 2.0f * d;   // fl(fl(zsum+enorm)-2*dot)
            if (se < best || (se == best && cc < bi)) { best = se; bi = cc; }
        }
    }

    // gather z_q + commitment-loss partial
    const float* erow = emb + (size_t)bi * DIM;
    float* qrow = zq + (size_t)r * DIM;
    float lacc = 0.f;
#pragma unroll
    for (int j = 0; j < 24; j++) {
        float q = erow[lane + j * 32];
        qrow[lane + j * 32] = q;
        float dd = zreg[j] - q;
        lacc = fmaf(dd, dd, lacc);
    }
#pragma unroll
    for (int o = 16; o > 0; o >>= 1) lacc += __shfl_down_sync(0xffffffffu, lacc, o);
    if (lane == 0) {
        ids_out[r] = (float)bi;
        redl[w] = lacc;
    }
    __syncthreads();
    if (threadIdx.x == 0) {
        float t = 0.f;
#pragma unroll
        for (int i = 0; i < 8; i++) t += redl[i];
        atomicAdd(&g_loss, t);
    }
}

__global__ void finalize_kernel(float* __restrict__ loss_out) {
    *loss_out = 0.25f * (g_loss / (float)((long long)NROWS * DIM));
}

// ---------------- launch ----------------
extern "C" void kernel_launch(void* const* d_in, const int* in_sizes, int n_in,
                              void* d_out, int out_size) {
    (void)in_sizes; (void)n_in; (void)out_size;
    const float* z   = (const float*)d_in[0];
    const float* emb = (const float*)d_in[1];
    float* out   = (float*)d_out;
    float* zq    = out;                              // [NROWS*DIM]
    float* idsf  = out + (size_t)NROWS * DIM;        // [NROWS]
    float* lossp = idsf + NROWS;                     // [1]

    __nv_bfloat16 *zhi_p, *ehi_p;
    float *zsum_p, *enorm_p;
    cudaGetSymbolAddress((void**)&zhi_p, g_zhi);
    cudaGetSymbolAddress((void**)&ehi_p, g_ehi);
    cudaGetSymbolAddress((void**)&zsum_p, g_zsum);
    cudaGetSymbolAddress((void**)&enorm_p, g_enorm);

    const int VQ_SMEM = 2 * STAGE + 128;            // 65664
    cudaFuncSetAttribute(vq_pass1_kernel, cudaFuncAttributeMaxDynamicSharedMemorySize, VQ_SMEM);

    prep_kernel<<<NROWS / 8, 256>>>(z, zhi_p, zsum_p, NROWS);
    prep_kernel<<<KC / 8, 256>>>(emb, ehi_p, enorm_p, KC);
    vq_pass1_kernel<<<NCTA, 128, VQ_SMEM>>>();
    refine_kernel<<<NROWS / 8, 256>>>(z, emb, idsf, zq);
    finalize_kernel<<<1, 1>>>(lossp);
}

// round 15
// speedup vs baseline: 1.2326x; 1.0274x over previous
#include <cuda_runtime.h>
#include <cuda_bf16.h>
#include <cstdint>
#include <climits>

#define DIM    768
#define KC     2048
#define NROWS  16384
#define BM     128               // rows per unit
#define BN     128               // codes per unit
#define BK     64                // bf16 elems per chunk = 128 B/row
#define CHUNKS (DIM / BK)        // 12
#define NUNITS ((NROWS / BM) * (KC / BN))  // 2048
#define NCTA   296               // 2 CTAs per SM exactly
#define STAGE  32768             // A 16KB + B 16KB
#define QSCALE 131072.0f
#define QTHR_Q 85                // refine window in quanta (~6.5e-4)

__device__ float g_enorm[KC];
__device__ float g_zsum[NROWS];
__device__ float g_loss;
__device__ int   g_cnt;
__device__ int   g_qmin[NROWS];
__device__ __nv_bfloat16 g_zhi[(size_t)NROWS * DIM];
__device__ __nv_bfloat16 g_ehi[(size_t)KC * DIM];
__device__ short g_si[(size_t)NROWS * KC];     // 64 MiB quantized scores

static __device__ __forceinline__ uint32_t smem_u32(const void* p) {
    uint32_t a;
    asm("{ .reg .u64 t; cvta.to.shared.u64 t, %1; cvt.u32.u64 %0, t; }" : "=r"(a) : "l"(p));
    return a;
}
#define CP_ASYNC16(dst, src) \
    asm volatile("cp.async.cg.shared.global [%0], [%1], 16;" :: "r"(dst), "l"(src))
#define CP_COMMIT() asm volatile("cp.async.commit_group;" ::: "memory")
#define LDMX4(r, addr) \
    asm volatile("ldmatrix.sync.aligned.m8n8.x4.shared.b16 {%0,%1,%2,%3}, [%4];" \
        : "=r"((r)[0]), "=r"((r)[1]), "=r"((r)[2]), "=r"((r)[3]) : "r"(addr))
#define MMA16816(d, a, b0_, b1_) \
    asm volatile("mma.sync.aligned.m16n8k16.row.col.f32.bf16.bf16.f32 " \
        "{%0,%1,%2,%3}, {%4,%5,%6,%7}, {%8,%9}, {%0,%1,%2,%3};" \
        : "+f"((d)[0]), "+f"((d)[1]), "+f"((d)[2]), "+f"((d)[3]) \
        : "r"((a)[0]), "r"((a)[1]), "r"((a)[2]), "r"((a)[3]), "r"(b0_), "r"(b1_))

// -------- merged prep: z + emb convert + norms + init (warp/row) --------
__global__ void prep_kernel(const float* __restrict__ z, const float* __restrict__ emb,
                            __nv_bfloat16* __restrict__ zd, __nv_bfloat16* __restrict__ ed) {
    int w    = (blockIdx.x * blockDim.x + threadIdx.x) >> 5;
    int lane = threadIdx.x & 31;
    if (w >= NROWS + KC) return;
    const bool isZ = (w < NROWS);
    const int row  = isZ ? w : (w - NROWS);
    const float2* s2 = (const float2*)((isZ ? z : emb) + (size_t)row * DIM);
    __nv_bfloat162* d2 = (__nv_bfloat162*)((isZ ? zd : ed) + (size_t)row * DIM);
    float acc = 0.f;
#pragma unroll
    for (int j = 0; j < DIM / 64; j++) {
        float2 v = s2[lane + j * 32];
        acc = fmaf(v.x, v.x, fmaf(v.y, v.y, acc));
        d2[lane + j * 32] = __halves2bfloat162(__float2bfloat16_rn(v.x),
                                               __float2bfloat16_rn(v.y));
    }
#pragma unroll
    for (int o = 16; o > 0; o >>= 1) acc += __shfl_down_sync(0xffffffffu, acc, o);
    if (lane == 0) {
        if (isZ) { g_zsum[row] = acc; g_qmin[row] = INT_MAX; }
        else     { g_enorm[row] = acc; }
        if (w == 0) { g_loss = 0.f; g_cnt = 0; }
    }
}

// -------- pass 1: persistent bf16 HMMA GEMM -> int16 scores + per-row qmin --------
// 296 persistent CTAs x 128 thr (exactly 2/SM). Unit = 128 rows x 128 codes,
// 12 K-chunk iterations; pipeline runs seamlessly across unit boundaries.
__global__ __launch_bounds__(128, 2)
void vq_pass1_kernel() {
    extern __shared__ char smem_raw[];
    const uint32_t sb = (smem_u32(smem_raw) + 127u) & ~127u;
    const int tid  = threadIdx.x;
    const int lane = tid & 31;
    const int w    = tid >> 5;
    const int wr   = w >> 1;    // 0..1  rows 64 each
    const int wc   = w & 1;     // 0..1  cols 64 each

    // ---- cp.async addressing: 16 x 16B per thread per stage ----
    const int gr  = tid >> 3;          // base row 0..15
    const int gg  = tid & 7;           // granule 0..7
    const uint32_t swx = (uint32_t)((gg ^ (gr & 7)) << 4);
    const uint32_t da  = (uint32_t)(gr * 128) + swx;            // A dst base
    const uint32_t db  = 16384u + (uint32_t)(gr * 128) + swx;   // B dst base
    const size_t aoff = (size_t)gr * DIM + gg * 8;

    // ---- ldmatrix lane addressing ----
    const int arow = lane & 15;
    const int agr  = lane >> 4;
    const int brow = (lane & 7) + ((lane >> 4) & 1) * 8;
    const int bgr  = (lane >> 3) & 1;
    uint32_t a_rt[4]; int a_sw[4];
#pragma unroll
    for (int mt = 0; mt < 4; mt++) {
        int r = wr * 64 + mt * 16 + arow;
        a_rt[mt] = r * 128; a_sw[mt] = r & 7;
    }
    uint32_t b_rt[4]; int b_sw[4];
#pragma unroll
    for (int nb = 0; nb < 4; nb++) {
        int r = wc * 64 + nb * 16 + brow;
        b_rt[nb] = r * 128; b_sw[nb] = r & 7;
    }

    float acc[4][8][4];
#pragma unroll
    for (int mt = 0; mt < 4; mt++)
#pragma unroll
        for (int nt = 0; nt < 8; nt++)
#pragma unroll
            for (int q = 0; q < 4; q++) acc[mt][nt][q] = 0.f;

    // prologue: issue (unit=blockIdx.x, chunk=0) into buf 0
    {
        const __nv_bfloat16* pa = g_zhi + (size_t)(blockIdx.x >> 4) * BM * DIM + aoff;
        const __nv_bfloat16* pb = g_ehi + (size_t)(blockIdx.x & 15) * BN * DIM + aoff;
#pragma unroll
        for (int k = 0; k < 8; k++)
            CP_ASYNC16(sb + da + (uint32_t)k * 2048u, pa + (size_t)k * 16 * DIM);
#pragma unroll
        for (int k = 0; k < 8; k++)
            CP_ASYNC16(sb + db + (uint32_t)k * 2048u, pb + (size_t)k * 16 * DIM);
        CP_COMMIT();
    }

    int cu = blockIdx.x, cc = 0;   // compute unit/chunk
    int pu = blockIdx.x, pc = 0;   // last-issued unit/chunk
    int it = 0;

    while (cu < NUNITS) {
        asm volatile("cp.async.wait_group 0;" ::: "memory");
        __syncthreads();

        if (++pc == CHUNKS) { pc = 0; pu += NCTA; }
        const bool donx = pu < NUNITS;
        const uint32_t nst = sb + (uint32_t)((it + 1) & 1) * STAGE;
        const __nv_bfloat16* npa = g_zhi + (size_t)(pu >> 4) * BM * DIM + aoff + pc * BK;
        const __nv_bfloat16* npb = g_ehi + (size_t)(pu & 15) * BN * DIM + aoff + pc * BK;

        const uint32_t Ab = sb + (uint32_t)(it & 1) * STAGE;
        const uint32_t Bb = Ab + 16384u;

        uint32_t ah[2][16];
#pragma unroll
        for (int mt = 0; mt < 4; mt++) {    // prefetch ks=0 A
            uint32_t ad = Ab + a_rt[mt] + (uint32_t)((agr ^ a_sw[mt]) << 4);
            LDMX4(&ah[0][mt * 4], ad);
        }

#pragma unroll
        for (int ks = 0; ks < 4; ks++) {
            const int g0 = ks * 2;
            const int cur = ks & 1, nxt = cur ^ 1;
            uint32_t bh[16];
#pragma unroll
            for (int nb = 0; nb < 4; nb++) {
                uint32_t bd = Bb + b_rt[nb] + (uint32_t)(((g0 + bgr) ^ b_sw[nb]) << 4);
                LDMX4(&bh[nb * 4], bd);
            }
            if (ks < 3) {
#pragma unroll
                for (int mt = 0; mt < 4; mt++) {
                    uint32_t ad = Ab + a_rt[mt] + (uint32_t)(((g0 + 2 + agr) ^ a_sw[mt]) << 4);
                    LDMX4(&ah[nxt][mt * 4], ad);
                }
            }
            if (donx) {
                if (ks < 2) {
#pragma unroll
                    for (int k = ks * 4; k < ks * 4 + 4; k++)
                        CP_ASYNC16(nst + da + (uint32_t)k * 2048u, npa + (size_t)k * 16 * DIM);
                } else {
#pragma unroll
                    for (int k = (ks - 2) * 4; k < (ks - 2) * 4 + 4; k++)
                        CP_ASYNC16(nst + db + (uint32_t)k * 2048u, npb + (size_t)k * 16 * DIM);
                }
            }
#pragma unroll
            for (int mt = 0; mt < 4; mt++)
#pragma unroll
                for (int nt = 0; nt < 8; nt++) {
                    const int bo_ = (nt >> 1) * 4 + (nt & 1) * 2;
                    MMA16816(acc[mt][nt], &ah[cur][mt * 4], bh[bo_], bh[bo_ + 1]);
                }
        }
        if (donx) CP_COMMIT();

        // ---- unit end: dequantize -> int16 store + per-row qmin ----
        if (cc == CHUNKS - 1) {
            const int rowB = (cu >> 4) * BM;
            const int colB = (cu & 15) * BN;
            int qmn[8];
#pragma unroll
            for (int sl = 0; sl < 8; sl++) qmn[sl] = 32767;
#pragma unroll
            for (int nt = 0; nt < 8; nt++) {
                int cb = colB + wc * 64 + nt * 8 + (lane & 3) * 2;
                float e0 = __ldg(&g_enorm[cb]);
                float e1 = __ldg(&g_enorm[cb + 1]);
#pragma unroll
                for (int mt = 0; mt < 4; mt++)
#pragma unroll
                    for (int h = 0; h < 2; h++) {
                        const int sl = mt * 2 + h;
                        float d0 = acc[mt][nt][h * 2], d1 = acc[mt][nt][h * 2 + 1];
                        int q0 = __float2int_rn(fminf(fmaxf((e0 - 2.0f * d0) * QSCALE, -32767.f), 32767.f));
                        int q1 = __float2int_rn(fminf(fmaxf((e1 - 2.0f * d1) * QSCALE, -32767.f), 32767.f));
                        int row0 = rowB + wr * 64 + mt * 16 + h * 8 + (lane >> 2);
                        *(short2*)&g_si[(size_t)row0 * KC + cb] =
                            make_short2((short)q0, (short)q1);
                        qmn[sl] = min(qmn[sl], min(q0, q1));
                        acc[mt][nt][h * 2] = 0.f;
                        acc[mt][nt][h * 2 + 1] = 0.f;
                    }
            }
#pragma unroll
            for (int off = 1; off <= 2; off <<= 1)
#pragma unroll
                for (int sl = 0; sl < 8; sl++)
                    qmn[sl] = min(qmn[sl], __shfl_xor_sync(0xffffffffu, qmn[sl], off));
            if ((lane & 3) == 0) {
#pragma unroll
                for (int sl = 0; sl < 8; sl++) {
                    int row0 = rowB + wr * 64 + (sl >> 1) * 16 + (sl & 1) * 8 + (lane >> 2);
                    atomicMin(&g_qmin[row0], qmn[sl]);
                }
            }
        }
        if (++cc == CHUNKS) { cc = 0; cu += NCTA; }
        ++it;
    }
}

// -------- refine: vectorized scan + exact argmin + gather + loss + finalize --------
__global__ __launch_bounds__(256)
void refine_kernel(const float* __restrict__ z, const float* __restrict__ emb,
                   float* __restrict__ ids_out, float* __restrict__ zq,
                   float* __restrict__ loss_out) {
    __shared__ float redl[8];
    const int w    = threadIdx.x >> 5;
    const int lane = threadIdx.x & 31;
    const int r    = blockIdx.x * 8 + w;

    const float zr = g_zsum[r];
    const int qthr = min(g_qmin[r] + QTHR_Q, 32767);
    const unsigned thr2 = ((unsigned)(unsigned short)qthr << 16) | (unsigned short)qthr;

    // z row in registers (exact fp32)
    float zreg[24];
    const float* zrow = z + (size_t)r * DIM;
#pragma unroll
    for (int j = 0; j < 24; j++) zreg[j] = zrow[lane + j * 32];

    // vectorized single-pass candidate scan: 16B per thread-iter, packed compares
    const int4* q4 = (const int4*)(g_si + (size_t)r * KC);
    int cand[4];
    int nc = 0;
#pragma unroll
    for (int j = 0; j < 8; j++) {
        int4 v = q4[lane + j * 32];
        unsigned m0 = __vcmples2((unsigned)v.x, thr2);
        unsigned m1 = __vcmples2((unsigned)v.y, thr2);
        unsigned m2 = __vcmples2((unsigned)v.z, thr2);
        unsigned m3 = __vcmples2((unsigned)v.w, thr2);
        if (m0 | m1 | m2 | m3) {
            const int base = (lane + j * 32) * 8;
            const unsigned mm[4] = {m0, m1, m2, m3};
#pragma unroll
            for (int t = 0; t < 4; t++) {
                if (mm[t] & 0xFFFFu) { if (nc < 4) cand[nc++] = base + t * 2; }
                if (mm[t] >> 16)     { if (nc < 4) cand[nc++] = base + t * 2 + 1; }
            }
        }
    }

    // warp-cooperative exact rescore (reference rounding, first-index ties)
    float best = 3.4e38f;
    int   bi   = INT_MAX;
    unsigned m = __ballot_sync(0xffffffffu, nc > 0);
    while (m) {
        int l = __ffs(m) - 1;
        m &= m - 1;
        int cnt = __shfl_sync(0xffffffffu, nc, l);
        for (int t = 0; t < cnt; t++) {
            int cc = __shfl_sync(0xffffffffu, cand[t], l);
            const float* erow = emb + (size_t)cc * DIM;
            float d = 0.f;
#pragma unroll
            for (int j = 0; j < 24; j++) d = fmaf(zreg[j], erow[lane + j * 32], d);
#pragma unroll
            for (int o = 16; o > 0; o >>= 1) d += __shfl_xor_sync(0xffffffffu, d, o);
            float se = (zr + g_enorm[cc]) - 2.0f * d;   // fl(fl(zsum+enorm)-2*dot)
            if (se < best || (se == best && cc < bi)) { best = se; bi = cc; }
        }
    }

    // gather z_q + commitment-loss partial
    const float* erow = emb + (size_t)bi * DIM;
    float* qrow = zq + (size_t)r * DIM;
    float lacc = 0.f;
#pragma unroll
    for (int j = 0; j < 24; j++) {
        float q = erow[lane + j * 32];
        qrow[lane + j * 32] = q;
        float dd = zreg[j] - q;
        lacc = fmaf(dd, dd, lacc);
    }
#pragma unroll
    for (int o = 16; o > 0; o >>= 1) lacc += __shfl_down_sync(0xffffffffu, lacc, o);
    if (lane == 0) {
        ids_out[r] = (float)bi;
        redl[w] = lacc;
    }
    __syncthreads();
    if (threadIdx.x == 0) {
        float t = 0.f;
#pragma unroll
        for (int i = 0; i < 8; i++) t += redl[i];
        atomicAdd(&g_loss, t);
        __threadfence();
        int old = atomicAdd(&g_cnt, 1);
        if (old == gridDim.x - 1) {
            float total = atomicAdd(&g_loss, 0.f);
            *loss_out = 0.25f * (total / (float)((long long)NROWS * DIM));
        }
    }
}

// ---------------- launch ----------------
extern "C" void kernel_launch(void* const* d_in, const int* in_sizes, int n_in,
                              void* d_out, int out_size) {
    (void)in_sizes; (void)n_in; (void)out_size;
    const float* z   = (const float*)d_in[0];
    const float* emb = (const float*)d_in[1];
    float* out   = (float*)d_out;
    float* zq    = out;                              // [NROWS*DIM]
    float* idsf  = out + (size_t)NROWS * DIM;        // [NROWS]
    float* lossp = idsf + NROWS;                     // [1]

    __nv_bfloat16 *zhi_p, *ehi_p;
    cudaGetSymbolAddress((void**)&zhi_p, g_zhi);
    cudaGetSymbolAddress((void**)&ehi_p, g_ehi);

    const int VQ_SMEM = 2 * STAGE + 128;            // 65664
    cudaFuncSetAttribute(vq_pass1_kernel, cudaFuncAttributeMaxDynamicSharedMemorySize, VQ_SMEM);

    prep_kernel<<<(NROWS + KC) / 8, 256>>>(z, emb, zhi_p, ehi_p);
    vq_pass1_kernel<<<NCTA, 128, VQ_SMEM>>>();
    refine_kernel<<<NROWS / 8, 256>>>(z, emb, idsf, zq, lossp);
}